// round 16
// baseline (speedup 1.0000x reference)
#include <cuda_runtime.h>
#include <cstdint>

// GTConvAE — dataflow persistent kernel, R16. Interior grid barriers replaced by
// fine-grained producer counters (release/acquire); per-layer buffers remove WAR
// hazards. One full barrier at kernel end + counter reset for graph-replay safety.
// Kronecker identity: S^k x[tau] = sum_{a,b<3} c_k[a][b] * Sg^b x[(tau-a) mod t].
// Layer = two GEMMs (G1=Sg@act, G2=Sg2@act) + 9-term combine with folded filters.

#define NN  192
#define TT  32
#define NB  128
#define KS  196

// ---------------- buffers (one per layer product; no aliasing) -------------------
__device__ float g_Sg2 [NN * NN];
__device__ float g_P   [TT * NN];     // P[tau][n] = (Sg@X) act layout
__device__ float g_actA[256 * NN];    // e1 out: row = tp*16+o
__device__ float g_G1e [256 * NN];    // e2 G1: row j = act-row index
__device__ float g_G2e [256 * NN];
__device__ float g_actB[256 * NN];    // e2 out: row = tp*32+o
__device__ float g_G1d [256 * NN];
__device__ float g_G2d [256 * NN];
__device__ float g_actC[256 * NN];    // d1 out: row = tau*16+o
__device__ float g_G1f [256 * NN];
__device__ float g_G2f [256 * NN];

// ---------------- counters (stride 32 words = 1 line each) -----------------------
__device__ unsigned g_c_sg2 [8 * 32];   // per m-band (24 rows); target 12
__device__ unsigned g_c_P;              // target 16
__device__ unsigned g_c_actA[16 * 32];  // per tp (16 rows);      target 8
__device__ unsigned g_c_Ge  [16 * 32];  // mat*8 + jtile(32 rows); target 8
__device__ unsigned g_c_actB[8 * 32];   // per tp (32 rows);      target 16
__device__ unsigned g_c_Gd  [16 * 32];  // target 8
__device__ unsigned g_c_actC[16 * 32];  // per tau (16 rows);     target 8
__device__ unsigned g_c_Gf  [16 * 32];  // target 8
__device__ unsigned g_cnt = 0;
__device__ unsigned g_gen = 0;

// ---------------- sync primitives ------------------------------------------------
__device__ __forceinline__ void arrive_ctr(unsigned* c)
{
    unsigned d;
    asm volatile("atom.release.gpu.add.u32 %0, [%1], %2;"
                 : "=r"(d) : "l"(c), "r"(1u) : "memory");
}
__device__ __forceinline__ void spin_ctr(const unsigned* c, unsigned tgt)
{
    unsigned v;
    do {
        asm volatile("ld.acquire.gpu.u32 %0, [%1];"
                     : "=r"(v) : "l"(c) : "memory");
    } while (v < tgt);
}
__device__ __forceinline__ unsigned bar_arrive()
{
    unsigned gen;
    asm volatile("ld.relaxed.gpu.u32 %0, [%1];"
                 : "=r"(gen) : "l"(&g_gen) : "memory");
    unsigned prev;
    asm volatile("atom.release.gpu.add.u32 %0, [%1], %2;"
                 : "=r"(prev) : "l"(&g_cnt), "r"(1u) : "memory");
    if (prev == NB - 1) {
        asm volatile("st.relaxed.gpu.u32 [%0], %1;"
                     :: "l"(&g_cnt), "r"(0u) : "memory");
        asm volatile("st.release.gpu.u32 [%0], %1;"
                     :: "l"(&g_gen), "r"(gen + 1u) : "memory");
    }
    return gen + 1;
}
__device__ __forceinline__ void bar_wait(unsigned target)
{
    unsigned cur;
    do {
        asm volatile("ld.acquire.gpu.u32 %0, [%1];"
                     : "=r"(cur) : "l"(&g_gen) : "memory");
    } while ((int)(cur - target) < 0);
}

// ---------------- cp.async helpers ----------------------------------------------
__device__ __forceinline__ void cp16(float* dst, const float* src, bool cg)
{
    uint32_t d = (uint32_t)__cvta_generic_to_shared(dst);
    if (cg)
        asm volatile("cp.async.cg.shared.global [%0], [%1], 16;" :: "r"(d), "l"(src));
    else
        asm volatile("cp.async.ca.shared.global [%0], [%1], 16;" :: "r"(d), "l"(src));
}
__device__ __forceinline__ void cp_wait_all()
{
    asm volatile("cp.async.wait_all;" ::: "memory");
}

// ---------------- tile loaders (128 threads) -------------------------------------
__device__ __forceinline__ void loadA24(const float* __restrict__ A, int m0,
                                        bool cg, float* As)
{
    #pragma unroll
    for (int r = 0; r < 9; r++) {
        int op = threadIdx.x + 128 * r;
        int ml = op / 48, kq = op - ml * 48;
        cp16(&As[ml * KS + 4 * kq], &A[(m0 + ml) * NN + 4 * kq], cg);
    }
}
__device__ __forceinline__ void loadB16(const float* __restrict__ Bg, int j0,
                                        float* Bsb)
{
    #pragma unroll
    for (int r = 0; r < 6; r++) {
        int op = threadIdx.x + 128 * r;
        int jl = op / 48, kq = op - jl * 48;
        cp16(&Bsb[jl * KS + 4 * kq], &Bg[(j0 + jl) * NN + 4 * kq], true);
    }
}

// ---------------- compute one 24m x 16j tile (128 threads) -----------------------
template <bool CROW>
__device__ __forceinline__ void tile_compute(const float* __restrict__ As,
                                             const float* __restrict__ Bsb,
                                             float* __restrict__ C, int m0, int j0)
{
    const int tid = threadIdx.x;
    const int tx = tid & 15, ty = tid >> 4;
    float acc0 = 0.f, acc1 = 0.f, acc2 = 0.f;
    const float* bp  = Bsb + tx * KS;
    const float* ap0 = As + ty * KS;
    const float* ap1 = ap0 + 8 * KS;
    const float* ap2 = ap0 + 16 * KS;
    #pragma unroll 8
    for (int k = 0; k < NN; k += 4) {
        float4 b  = *(const float4*)(bp + k);
        float4 a0 = *(const float4*)(ap0 + k);
        float4 a1 = *(const float4*)(ap1 + k);
        float4 a2 = *(const float4*)(ap2 + k);
        acc0 += a0.x * b.x; acc0 += a0.y * b.y; acc0 += a0.z * b.z; acc0 += a0.w * b.w;
        acc1 += a1.x * b.x; acc1 += a1.y * b.y; acc1 += a1.z * b.z; acc1 += a1.w * b.w;
        acc2 += a2.x * b.x; acc2 += a2.y * b.y; acc2 += a2.z * b.z; acc2 += a2.w * b.w;
    }
    const int j = j0 + tx;
    if (CROW) {
        C[(m0 + ty     ) * NN + j] = acc0;
        C[(m0 + ty +  8) * NN + j] = acc1;
        C[(m0 + ty + 16) * NN + j] = acc2;
    } else {
        C[j * NN + m0 + ty     ] = acc0;
        C[j * NN + m0 + ty +  8] = acc1;
        C[j * NN + m0 + ty + 16] = acc2;
    }
}

// ---------------- big GEMM stage: 2 j-tiles, double-buffered B -------------------
__device__ void big_stage(const float* __restrict__ Bact,
                          float* __restrict__ C, int m0, int j0,
                          float* As, float* Bs0, float* Bs1)
{
    loadB16(Bact, j0, Bs0);
    cp_wait_all(); __syncthreads();
    loadB16(Bact, j0 + 16, Bs1);
    tile_compute<false>(As, Bs0, C, m0, j0);
    cp_wait_all(); __syncthreads();
    tile_compute<false>(As, Bs1, C, m0, j0 + 16);
}

// ---------------- S0 tile: B from column-slices (Sg or X) ------------------------
template <int BMODE, bool CROW>   // 1: Sg cols, 2: X cols
__device__ void s0_tile(const float* __restrict__ A, const float* __restrict__ Bg,
                        int j0, float* __restrict__ C, int m0,
                        float* As, float* Bs0)
{
    loadA24(A, m0, false, As);
    const int tid = threadIdx.x;
    #pragma unroll
    for (int r = 0; r < 24; r++) {
        int idx = tid + 128 * r;
        int jl = idx & 15, kk = idx >> 4;
        Bs0[jl * KS + kk] = (BMODE == 1) ? Bg[kk * NN + j0 + jl]
                                         : Bg[kk * TT + j0 + jl];
    }
    cp_wait_all(); __syncthreads();
    tile_compute<CROW>(As, Bs0, C, m0, j0);
}

// ---------------- folded filters -------------------------------------------------
__device__ __forceinline__ float fold_H(const float* __restrict__ h3,
                                        const float sv[4], int a, int b)
{
    float c0 = (a == 0 && b == 0) ? 1.f : 0.f;
    float c1 = (a < 2 && b < 2) ? sv[a * 2 + b] : 0.f;
    float c2 = 0.f;
    #pragma unroll
    for (int a1 = 0; a1 < 2; a1++)
        #pragma unroll
        for (int b1 = 0; b1 < 2; b1++) {
            int a2 = a - a1, b2 = b - b1;
            if (a2 >= 0 && a2 < 2 && b2 >= 0 && b2 < 2)
                c2 += sv[a1 * 2 + b1] * sv[a2 * 2 + b2];
        }
    return h3[0] * c0 + h3[1] * c1 + h3[2] * c2;
}
__device__ __forceinline__ void build_Hs(float* Hs, const float* __restrict__ h,
                                         const float sv[4], int CI, int OT, int ob)
{
    for (int idx = threadIdx.x; idx < CI * 9 * OT; idx += 128) {
        int oo = idx % OT;
        int tmp = idx / OT;
        int b = tmp % 3, a = (tmp / 3) % 3, i = tmp / 9;
        Hs[idx] = fold_H(&h[((ob + oo) * CI + i) * 3], sv, a, b);
    }
}

// ---------------- combine bodies (Hs prebuilt; float2; 96 threads) ---------------
template <int CI, int CO, int OT>
__device__ void combine_enc_body(const float* __restrict__ G0,
                                 const float* __restrict__ G1,
                                 const float* __restrict__ G2,
                                 float* __restrict__ out, int t, int tp, int ob,
                                 const float* Hs)
{
    const int tid = threadIdx.x;
    if (tid < 96) {
        const int n2 = 2 * tid;
        float2 acc0[OT], acc1[OT];
        #pragma unroll
        for (int o = 0; o < OT; o++) {
            acc0[o] = make_float2(0.f, 0.f); acc1[o] = make_float2(0.f, 0.f);
        }
        #pragma unroll
        for (int tt = 0; tt < 4; tt++) {
            int src = (2 * tp - 2 + tt + t) & (t - 1);
            #pragma unroll
            for (int i = 0; i < CI; i++) {
                float2 v0 = __ldcg((const float2*)&G0[(src * CI + i) * NN + n2]);
                float2 v1 = __ldcg((const float2*)&G1[(src * CI + i) * NN + n2]);
                float2 v2 = __ldcg((const float2*)&G2[(src * CI + i) * NN + n2]);
                if (tt <= 2) {
                    const float* Hp = &Hs[(i * 3 + (2 - tt)) * 3 * OT];
                    #pragma unroll
                    for (int o = 0; o < OT; o++) {
                        float h0 = Hp[o], h1 = Hp[OT + o], h2 = Hp[2 * OT + o];
                        acc0[o].x += h0 * v0.x + h1 * v1.x + h2 * v2.x;
                        acc0[o].y += h0 * v0.y + h1 * v1.y + h2 * v2.y;
                    }
                }
                if (tt >= 1) {
                    const float* Hp = &Hs[(i * 3 + (3 - tt)) * 3 * OT];
                    #pragma unroll
                    for (int o = 0; o < OT; o++) {
                        float h0 = Hp[o], h1 = Hp[OT + o], h2 = Hp[2 * OT + o];
                        acc1[o].x += h0 * v0.x + h1 * v1.x + h2 * v2.x;
                        acc1[o].y += h0 * v0.y + h1 * v1.y + h2 * v2.y;
                    }
                }
            }
        }
        #pragma unroll
        for (int o = 0; o < OT; o++) {
            float2 r;
            r.x = fmaxf(fmaxf(acc0[o].x, acc1[o].x), 0.f);
            r.y = fmaxf(fmaxf(acc0[o].y, acc1[o].y), 0.f);
            *(float2*)&out[(tp * CO + ob + o) * NN + n2] = r;
        }
    }
}

template <int CI, int CO, int OT>
__device__ void combine_dec_body(const float* __restrict__ G0,
                                 const float* __restrict__ G1,
                                 const float* __restrict__ G2,
                                 float* __restrict__ out, int t, int tau, int ob,
                                 const float* Hs)
{
    const int tid = threadIdx.x;
    if (tid < 96) {
        const int n2 = 2 * tid;
        float2 acc[OT];
        #pragma unroll
        for (int o = 0; o < OT; o++) acc[o] = make_float2(0.f, 0.f);
        #pragma unroll
        for (int a = 0; a < 3; a++) {
            int src = tau - a; if (src < 0) src += t;
            if (src & 1) continue;
            int tl = src >> 1;
            #pragma unroll 16
            for (int i = 0; i < CI; i++) {
                float2 v0 = __ldcg((const float2*)&G0[(tl * CI + i) * NN + n2]);
                float2 v1 = __ldcg((const float2*)&G1[(tl * CI + i) * NN + n2]);
                float2 v2 = __ldcg((const float2*)&G2[(tl * CI + i) * NN + n2]);
                const float* Hp = &Hs[(i * 3 + a) * 3 * OT];
                #pragma unroll
                for (int o = 0; o < OT; o++) {
                    float h0 = Hp[o], h1 = Hp[OT + o], h2 = Hp[2 * OT + o];
                    acc[o].x += h0 * v0.x + h1 * v1.x + h2 * v2.x;
                    acc[o].y += h0 * v0.y + h1 * v1.y + h2 * v2.y;
                }
            }
        }
        #pragma unroll
        for (int o = 0; o < OT; o++) {
            float2 r;
            r.x = fmaxf(acc[o].x, 0.f);
            r.y = fmaxf(acc[o].y, 0.f);
            *(float2*)&out[(tau * CO + ob + o) * NN + n2] = r;
        }
    }
}

// ---------------- persistent dataflow kernel -------------------------------------
__global__ __launch_bounds__(128, 1) void mega(
    const float* __restrict__ X,    const float* __restrict__ Sg,
    const float* __restrict__ s,    const float* __restrict__ h_e1,
    const float* __restrict__ h_e2, const float* __restrict__ h_d1,
    const float* __restrict__ h_d2, float* __restrict__ out)
{
    __shared__ float As[24 * KS];
    __shared__ float Bs0[16 * KS];
    __shared__ float Bs1[16 * KS];
    __shared__ float Hs[576];
    __shared__ float G2s[96];

    const int bid = blockIdx.x;
    const int tid = threadIdx.x;

    const int mat = bid >> 6;
    const int sub = bid & 63;
    const int gm0 = (sub >> 3) * 24;
    const int gj0 = (sub & 7) * 32;
    const int gjt = sub & 7;              // 32-row j-tile index

    const float sv[4] = { s[0], s[1], s[2], s[3] };

    // ======== S0: Sg2 (96 tiles) + P (16 tiles) ========
    if (bid < 96) {
        int mb = bid / 12, jt = bid % 12;
        s0_tile<1, true>(Sg, Sg, jt * 16, g_Sg2, mb * 24, As, Bs0);
        __syncthreads();
        if (tid == 0) arrive_ctr(&g_c_sg2[mb * 32]);
    } else if (bid < 112) {
        int b2 = bid - 96;
        int mb = b2 >> 1, jt = b2 & 1;
        s0_tile<2, false>(Sg, X, jt * 16, g_P, mb * 24, As, Bs0);
        __syncthreads();
        if (tid == 0) arrive_ctr(&g_c_P);
    }
    __syncthreads();

    // ======== S1: e1 combine + fused mini-GEMM (needs only P) ========
    {
        const int tp = bid & 15, nb = bid >> 4;
        const int n0 = nb * 24;
        loadA24(Sg, n0, false, As);           // input; no dependency
        for (int idx = tid; idx < 144; idx += 128) {
            int o = idx & 15, ab = idx >> 4;
            Hs[idx] = fold_H(&h_e1[o * 3], sv, ab / 3, ab % 3);
        }
        if (tid == 0) spin_ctr(&g_c_P, 16);
        __syncthreads();
        #pragma unroll
        for (int r = 0; r < 2; r++) {         // P rows for the 4 source taus
            int op = tid + 128 * r;
            if (op < 192) {
                int ttl = op / 48, kq = op - ttl * 48;
                int src = (2 * tp - 2 + ttl + TT) & (TT - 1);
                cp16(&Bs0[ttl * KS + 4 * kq], &g_P[src * NN + 4 * kq], true);
            }
        }
        cp_wait_all(); __syncthreads();
        if (tid < 96) {                       // mini-GEMM: 24 n x 4 src
            int nl = tid % 24, st = tid / 24;
            float acc = 0.f;
            const float* ap = As + nl * KS;
            const float* bp = Bs0 + st * KS;
            #pragma unroll 12
            for (int k = 0; k < NN; k += 4) {
                float4 a = *(const float4*)(ap + k);
                float4 b = *(const float4*)(bp + k);
                acc += a.x * b.x; acc += a.y * b.y; acc += a.z * b.z; acc += a.w * b.w;
            }
            G2s[st * 24 + nl] = acc;
        }
        __syncthreads();
        if (tid < 96) {
            int nl = tid % 24, og = tid / 24;
            int n = n0 + nl;
            float acc0[4] = {0.f, 0.f, 0.f, 0.f};
            float acc1[4] = {0.f, 0.f, 0.f, 0.f};
            #pragma unroll
            for (int ttl = 0; ttl < 4; ttl++) {
                int src = (2 * tp - 2 + ttl + TT) & (TT - 1);
                float v0 = X[n * TT + src];
                float v1 = Bs0[ttl * KS + n];
                float v2 = G2s[ttl * 24 + nl];
                if (ttl <= 2) {
                    int a = 2 - ttl;
                    #pragma unroll
                    for (int oo = 0; oo < 4; oo++) {
                        int o = og * 4 + oo;
                        acc0[oo] += Hs[(a * 3 + 0) * 16 + o] * v0
                                  + Hs[(a * 3 + 1) * 16 + o] * v1
                                  + Hs[(a * 3 + 2) * 16 + o] * v2;
                    }
                }
                if (ttl >= 1) {
                    int a = 3 - ttl;
                    #pragma unroll
                    for (int oo = 0; oo < 4; oo++) {
                        int o = og * 4 + oo;
                        acc1[oo] += Hs[(a * 3 + 0) * 16 + o] * v0
                                  + Hs[(a * 3 + 1) * 16 + o] * v1
                                  + Hs[(a * 3 + 2) * 16 + o] * v2;
                    }
                }
            }
            #pragma unroll
            for (int oo = 0; oo < 4; oo++) {
                int o = og * 4 + oo;
                g_actA[(tp * 16 + o) * NN + n] = fmaxf(fmaxf(acc0[oo], acc1[oo]), 0.f);
            }
        }
        __syncthreads();
        if (tid == 0) arrive_ctr(&g_c_actA[tp * 32]);
    }

    // ======== S3: e2 GEMMs (A: Sg or Sg2 band; B: actA rows gj0..+31) ========
    {
        if (mat == 0) {
            loadA24(Sg, gm0, false, As);                   // prefetch during waits
            if (tid == 0) spin_ctr(&g_c_actA[(gjt * 2    ) * 32], 8);
            if (tid == 1) spin_ctr(&g_c_actA[(gjt * 2 + 1) * 32], 8);
            __syncthreads();
        } else {
            if (tid == 0) spin_ctr(&g_c_sg2[(gm0 / 24) * 32], 12);
            if (tid == 1) spin_ctr(&g_c_actA[(gjt * 2    ) * 32], 8);
            if (tid == 2) spin_ctr(&g_c_actA[(gjt * 2 + 1) * 32], 8);
            __syncthreads();
            loadA24(g_Sg2, gm0, true, As);
        }
        big_stage(g_actA, mat ? g_G2e : g_G1e, gm0, gj0, As, Bs0, Bs1);
        __syncthreads();
        if (tid == 0) arrive_ctr(&g_c_Ge[(mat * 8 + gjt) * 32]);
    }

    // ======== S4: combine e2 -> actB ========
    {
        const int tp = bid & 7, ob = (bid >> 3) * 2;
        build_Hs(Hs, h_e2, sv, 16, 2, ob);
        if (tid < 12) {
            int tt = tid & 3;
            int src = (2 * tp - 2 + tt + 16) & 15;
            if (tid < 4)       spin_ctr(&g_c_actA[src * 32], 8);
            else if (tid < 8)  spin_ctr(&g_c_Ge[(0 * 8 + (src >> 1)) * 32], 8);
            else               spin_ctr(&g_c_Ge[(1 * 8 + (src >> 1)) * 32], 8);
        }
        __syncthreads();
        combine_enc_body<16, 32, 2>(g_actA, g_G1e, g_G2e, g_actB, 16, tp, ob, Hs);
        __syncthreads();
        if (tid == 0) arrive_ctr(&g_c_actB[tp * 32]);
    }

    // ======== S5: d1 GEMMs (A resident; B: actB rows gj0..+31 = tp gjt) ========
    {
        if (tid == 0) spin_ctr(&g_c_actB[gjt * 32], 16);
        __syncthreads();
        big_stage(g_actB, mat ? g_G2d : g_G1d, gm0, gj0, As, Bs0, Bs1);
        __syncthreads();
        if (tid == 0) arrive_ctr(&g_c_Gd[(mat * 8 + gjt) * 32]);
    }

    // ======== S6: combine d1 -> actC ========
    {
        const int tau = bid & 15, ob = (bid >> 4) * 2;
        build_Hs(Hs, h_d1, sv, 32, 2, ob);
        // source tls: tau even -> {tau/2, (tau-2 mod 16)/2}; odd -> {(tau-1)/2}
        int tl0, tl1, ntl;
        if (tau & 1) { tl0 = (tau - 1) >> 1; tl1 = tl0; ntl = 1; }
        else { tl0 = tau >> 1; tl1 = ((tau - 2 + 16) & 15) >> 1; ntl = 2; }
        if (tid == 0) spin_ctr(&g_c_actB[tl0 * 32], 16);
        if (tid == 1) spin_ctr(&g_c_Gd[(0 * 8 + tl0) * 32], 8);
        if (tid == 2) spin_ctr(&g_c_Gd[(1 * 8 + tl0) * 32], 8);
        if (ntl == 2) {
            if (tid == 3) spin_ctr(&g_c_actB[tl1 * 32], 16);
            if (tid == 4) spin_ctr(&g_c_Gd[(0 * 8 + tl1) * 32], 8);
            if (tid == 5) spin_ctr(&g_c_Gd[(1 * 8 + tl1) * 32], 8);
        }
        __syncthreads();
        combine_dec_body<32, 16, 2>(g_actB, g_G1d, g_G2d, g_actC, 16, tau, ob, Hs);
        __syncthreads();
        if (tid == 0) arrive_ctr(&g_c_actC[tau * 32]);
    }

    // ======== S7: d2 GEMMs (A resident; B: actC rows gj0..+31 = 2 taus) ========
    {
        if (tid == 0) spin_ctr(&g_c_actC[(gjt * 2    ) * 32], 8);
        if (tid == 1) spin_ctr(&g_c_actC[(gjt * 2 + 1) * 32], 8);
        __syncthreads();
        big_stage(g_actC, mat ? g_G2f : g_G1f, gm0, gj0, As, Bs0, Bs1);
        __syncthreads();
        if (tid == 0) arrive_ctr(&g_c_Gf[(mat * 8 + gjt) * 32]);
    }

    // ======== S8: final combine -> out (blocks < 32) ========
    if (bid < 32) {
        const int tau = bid;
        for (int idx = tid; idx < 144; idx += 128) {   // CI=16, OT=1
            int b = idx % 3, a = (idx / 3) % 3, i = idx / 9;
            Hs[idx] = fold_H(&h_d2[i * 3], sv, a, b);
        }
        int tl0, tl1, ntl;
        if (tau & 1) { tl0 = (tau - 1) >> 1; tl1 = tl0; ntl = 1; }
        else { tl0 = tau >> 1; tl1 = ((tau - 2 + 32) & 31) >> 1; ntl = 2; }
        if (tid == 0) spin_ctr(&g_c_actC[tl0 * 32], 8);
        if (tid == 1) spin_ctr(&g_c_Gf[(0 * 8 + (tl0 >> 1)) * 32], 8);
        if (tid == 2) spin_ctr(&g_c_Gf[(1 * 8 + (tl0 >> 1)) * 32], 8);
        if (ntl == 2) {
            if (tid == 3) spin_ctr(&g_c_actC[tl1 * 32], 8);
            if (tid == 4) spin_ctr(&g_c_Gf[(0 * 8 + (tl1 >> 1)) * 32], 8);
            if (tid == 5) spin_ctr(&g_c_Gf[(1 * 8 + (tl1 >> 1)) * 32], 8);
        }
        __syncthreads();
        if (tid < 96) {
            const int n2 = 2 * tid;
            float2 acc = make_float2(0.f, 0.f);
            #pragma unroll
            for (int a = 0; a < 3; a++) {
                int src = tau - a; if (src < 0) src += TT;
                if (src & 1) continue;
                int tl = src >> 1;
                #pragma unroll
                for (int i = 0; i < 16; i++) {
                    float2 v0 = __ldcg((const float2*)&g_actC[(tl * 16 + i) * NN + n2]);
                    float2 v1 = __ldcg((const float2*)&g_G1f[(tl * 16 + i) * NN + n2]);
                    float2 v2 = __ldcg((const float2*)&g_G2f[(tl * 16 + i) * NN + n2]);
                    float h0 = Hs[(i * 3 + a) * 3 + 0];
                    float h1 = Hs[(i * 3 + a) * 3 + 1];
                    float h2 = Hs[(i * 3 + a) * 3 + 2];
                    acc.x += h0 * v0.x + h1 * v1.x + h2 * v2.x;
                    acc.y += h0 * v0.y + h1 * v1.y + h2 * v2.y;
                }
            }
            out[(n2    ) * TT + tau] = acc.x;
            out[(n2 + 1) * TT + tau] = acc.y;
        }
    }

    // ======== final full barrier + counter reset (replay safety) ========
    __syncthreads();
    unsigned bg = 0;
    if (tid == 0) { bg = bar_arrive(); bar_wait(bg); }
    __syncthreads();
    if (bid == 0) {
        for (int i = tid; i < 8 * 32; i += 128)  g_c_sg2[i]  = 0;
        for (int i = tid; i < 16 * 32; i += 128) g_c_actA[i] = 0;
        for (int i = tid; i < 16 * 32; i += 128) g_c_Ge[i]   = 0;
        for (int i = tid; i < 8 * 32; i += 128)  g_c_actB[i] = 0;
        for (int i = tid; i < 16 * 32; i += 128) g_c_Gd[i]   = 0;
        for (int i = tid; i < 16 * 32; i += 128) g_c_actC[i] = 0;
        for (int i = tid; i < 16 * 32; i += 128) g_c_Gf[i]   = 0;
        if (tid == 0) g_c_P = 0;
    }
}

// ---------------- launch ---------------------------------------------------------
extern "C" void kernel_launch(void* const* d_in, const int* in_sizes, int n_in,
                              void* d_out, int out_size)
{
    const float* X    = (const float*)d_in[0];
    const float* Sg   = (const float*)d_in[1];
    const float* s    = (const float*)d_in[2];
    const float* h_e1 = (const float*)d_in[3];
    const float* h_e2 = (const float*)d_in[4];
    const float* h_d1 = (const float*)d_in[5];
    const float* h_d2 = (const float*)d_in[6];
    float* out = (float*)d_out;

    mega<<<NB, 128>>>(X, Sg, s, h_e1, h_e2, h_d1, h_d2, out);
}